// round 9
// baseline (speedup 1.0000x reference)
#include <cuda_runtime.h>
#include <math.h>

#define NN 100000
#define EE 1600000
#define GG 2000
#define NBLK 148
#define NTHR 512
#define NWARP (NBLK * NTHR / 32)

// ---------------- scratch (device globals; allocation-free) ----------------
__device__ float g_bufA[NN * 128];
__device__ float g_bufB[NN * 128];
__device__ float g_a9[NN * 9];
__device__ float g_dinv[NN];
__device__ int   g_deg[NN];
__device__ int   g_rowptr[NN + 1];
__device__ int   g_cursor[NN];
__device__ int2  g_edge[EE];            // {src, __float_as_int(norm)}
__device__ float g_usum[GG];
__device__ float g_ucnt[GG];
__device__ int   g_part[NBLK];
__device__ unsigned long long g_arrive;          // cumulative arrivals (persists across replays)
__device__ volatile unsigned  g_release;         // cumulative completed rounds

// ---------------- helpers ----------------
typedef unsigned long long ull;

__device__ __forceinline__ ull f2pack(float lo, float hi) {
    ull r;
    asm("mov.b64 %0, {%1, %2};" : "=l"(r) : "f"(lo), "f"(hi));
    return r;
}
__device__ __forceinline__ ull f2fma(ull a, ull b, ull c) {
    ull d;
    asm("fma.rn.f32x2 %0, %1, %2, %3;" : "=l"(d) : "l"(a), "l"(b), "l"(c));
    return d;
}
__device__ __forceinline__ void f2unpack(ull v, float& lo, float& hi) {
    asm("mov.b64 {%0, %1}, %2;" : "=f"(lo), "=f"(hi) : "l"(v));
}

// precise tanh (matches the round-2 passing kernel's numerics)
__device__ __forceinline__ float ftanh(float x) { return tanhf(x); }

// ---------------- grid barrier (cumulative, replay-safe) ----------------
__device__ __forceinline__ void gsync(unsigned target) {
    __threadfence();
    __syncthreads();
    if (threadIdx.x == 0) {
        ull a = atomicAdd(&g_arrive, 1ULL) + 1ULL;
        if ((a % (ull)NBLK) == 0ULL)
            g_release = (unsigned)(a / (ull)NBLK);
        while (g_release < target) __nanosleep(64);
        __threadfence();
    }
    __syncthreads();
}

// ---------------- GEMM: C = tanh(A[n x 128] @ W[128 x 128] + bias) ----------------
// Tile: 128 nodes x 128 cols per block iteration.
// Thread = 8 nodes (ty*8..+7) x 4 cols {tx, tx+32, tx+64, tx+96}.
//   512 threads * 32 outputs = 16384 = 128*128  -- full tile covered.
// W staged in smem f-pair-interleaved: Wp[fp*128+c] = (W[2fp][c], W[2fp+1][c]);
// LDS.64 lane-stride 8B (conflict-free). acc[j][k] = (even-f sum, odd-f sum) for
// node m0+j, col tx+32k; lo+hi added at epilogue.
__device__ __forceinline__ void gemm128_tanh(const float* __restrict__ A,
                                             const float* __restrict__ W,
                                             const float* __restrict__ bias,
                                             float* __restrict__ C, int n,
                                             ull* WpU, float* bs) {
    const int tid = threadIdx.x;
    {
        float2* Wp = (float2*)WpU;
        for (int i = tid; i < 64 * 128; i += NTHR) {
            int fp = i >> 7, c = i & 127;
            Wp[i] = make_float2(W[(2 * fp) * 128 + c], W[(2 * fp + 1) * 128 + c]);
        }
        if (tid < 128) bs[tid] = bias[tid];
    }
    __syncthreads();

    const int tx = tid & 31;      // cols tx, tx+32, tx+64, tx+96
    const int ty = tid >> 5;      // nodes ty*8 .. ty*8+7 within tile
    const int ntile = (n + 127) >> 7;
    const float4* A4 = (const float4*)A;

    for (int t = blockIdx.x; t < ntile; t += NBLK) {
        const int m0 = t * 128 + ty * 8;
        int mi[8];
#pragma unroll
        for (int j = 0; j < 8; j++) {
            int m = m0 + j;
            mi[j] = (m < n) ? m : (n - 1);
        }
        ull acc[8][4];
#pragma unroll
        for (int j = 0; j < 8; j++)
#pragma unroll
            for (int k = 0; k < 4; k++) acc[j][k] = 0ULL;

        for (int fg = 0; fg < 32; fg++) {
            ull WA[4], WB[4];
#pragma unroll
            for (int k = 0; k < 4; k++) {
                WA[k] = WpU[(2 * fg) * 128 + tx + 32 * k];       // f = 4fg, 4fg+1
                WB[k] = WpU[(2 * fg + 1) * 128 + tx + 32 * k];   // f = 4fg+2, 4fg+3
            }
#pragma unroll
            for (int j = 0; j < 8; j++) {
                float4 a = A4[mi[j] * 32 + fg];   // warp-uniform broadcast
                ull pa = f2pack(a.x, a.y);
                ull pb = f2pack(a.z, a.w);
#pragma unroll
                for (int k = 0; k < 4; k++) {
                    acc[j][k] = f2fma(pa, WA[k], acc[j][k]);
                    acc[j][k] = f2fma(pb, WB[k], acc[j][k]);
                }
            }
        }

#pragma unroll
        for (int j = 0; j < 8; j++) {
            int m = m0 + j;
            if (m < n) {
#pragma unroll
                for (int k = 0; k < 4; k++) {
                    float lo, hi;
                    f2unpack(acc[j][k], lo, hi);
                    int c = tx + 32 * k;
                    C[m * 128 + c] = ftanh(lo + hi + bs[c]);
                }
            }
        }
    }
    __syncthreads();
}

// warp-per-node 128-wide gather-aggregate
__device__ __forceinline__ void agg128(const float* __restrict__ h, float* __restrict__ out,
                                       int n) {
    int gw = (blockIdx.x * NTHR + threadIdx.x) >> 5;
    int lane = threadIdx.x & 31;
    const float4* h4 = (const float4*)h;
    for (int w = gw; w < n; w += NWARP) {
        float d = g_dinv[w];
        float sn = d * d;
        float4 v = h4[w * 32 + lane];
        float ax = v.x * sn, ay = v.y * sn, az = v.z * sn, aw = v.w * sn;
        int e = g_rowptr[w], end = g_rowptr[w + 1];
        for (; e + 4 <= end; e += 4) {
            int2 m0 = g_edge[e],     m1 = g_edge[e + 1];
            int2 m2 = g_edge[e + 2], m3 = g_edge[e + 3];
            float e0 = __int_as_float(m0.y), e1 = __int_as_float(m1.y);
            float e2 = __int_as_float(m2.y), e3 = __int_as_float(m3.y);
            float4 u0 = h4[m0.x * 32 + lane];
            float4 u1 = h4[m1.x * 32 + lane];
            float4 u2 = h4[m2.x * 32 + lane];
            float4 u3 = h4[m3.x * 32 + lane];
            ax += u0.x * e0; ay += u0.y * e0; az += u0.z * e0; aw += u0.w * e0;
            ax += u1.x * e1; ay += u1.y * e1; az += u1.z * e1; aw += u1.w * e1;
            ax += u2.x * e2; ay += u2.y * e2; az += u2.z * e2; aw += u2.w * e2;
            ax += u3.x * e3; ay += u3.y * e3; az += u3.z * e3; aw += u3.w * e3;
        }
        for (; e < end; e++) {
            int2 m = g_edge[e];
            float wt = __int_as_float(m.y);
            float4 u = h4[m.x * 32 + lane];
            ax += u.x * wt; ay += u.y * wt; az += u.z * wt; aw += u.w * wt;
        }
        float4 o; o.x = ax; o.y = ay; o.z = az; o.w = aw;
        ((float4*)out)[w * 32 + lane] = o;
    }
}

// ---------------- the mega kernel ----------------
__global__ void __launch_bounds__(NTHR, 1)
mega(const float* __restrict__ x, const int* __restrict__ ei, const int* __restrict__ batch,
     const int* __restrict__ ia, const int* __restrict__ ib,
     const float* __restrict__ W_in, const float* __restrict__ b_in,
     const float* __restrict__ W1, const float* __restrict__ b1,
     const float* __restrict__ W2, const float* __restrict__ b2,
     const float* __restrict__ Wf1, const float* __restrict__ bf1,
     const float* __restrict__ Wf2, const float* __restrict__ bf2,
     const float* __restrict__ Wf3, const float* __restrict__ bf3,
     float* __restrict__ out, int n, int E, int P, int G) {
    extern __shared__ unsigned char smraw[];
    ull*   WpU = (ull*)smraw;                      // 64 KB weight stage
    float* bs  = (float*)(smraw + 65536);          // 512 B bias / small params
    int*   sci = (int*)(smraw + 65536);            // 2 KB scan scratch (phase-disjoint)

    const int tid = threadIdx.x;
    const int bid = blockIdx.x;
    const int gt  = bid * NTHR + tid;
    const int GSTRIDE = NBLK * NTHR;
    const int lane = tid & 31;
    const int gw = gt >> 5;
    const int* src = ei;
    const int* dst = ei + E;

    __shared__ unsigned s_base;
    if (tid == 0) s_base = g_release;
    __syncthreads();
    const unsigned base = s_base;
    unsigned rnd = 0;

    // ---- P0: zero deg, a9, pooled sums ----
    for (int i = gt; i < n; i += GSTRIDE) g_deg[i] = 0;
    for (int i = gt; i < n * 9; i += GSTRIDE) g_a9[i] = 0.0f;
    if (gt < G) { g_usum[gt] = 0.0f; g_ucnt[gt] = 0.0f; }
    gsync(base + ++rnd);

    // ---- P1: in-degree count ----
    for (int e = gt; e < E; e += GSTRIDE) atomicAdd(&g_deg[dst[e]], 1);
    gsync(base + ++rnd);

    // ---- P2: block-local scan of deg -> rowptr (local excl), dinv, partials ----
    {
        const int CH = (n + NBLK - 1) / NBLK;
        const int bbase = bid * CH;
        const int lim = (bbase + CH < n) ? bbase + CH : n;
        int i0 = bbase + 2 * tid, i1 = i0 + 1;
        int v0 = (i0 < lim) ? g_deg[i0] : 0;
        int v1 = (i1 < lim) ? g_deg[i1] : 0;
        if (i0 < lim) g_dinv[i0] = rsqrtf((float)v0 + 1.0f);
        if (i1 < lim) g_dinv[i1] = rsqrtf((float)v1 + 1.0f);
        int s = v0 + v1;
        sci[tid] = s;
        __syncthreads();
        for (int off = 1; off < NTHR; off <<= 1) {
            int t_ = (tid >= off) ? sci[tid - off] : 0;
            __syncthreads();
            sci[tid] += t_;
            __syncthreads();
        }
        int exc = sci[tid] - s;
        if (i0 < lim) g_rowptr[i0] = exc;
        if (i1 < lim) g_rowptr[i1] = exc + v0;
        if (tid == NTHR - 1) g_part[bid] = sci[NTHR - 1];
    }
    gsync(base + ++rnd);

    // ---- P3: block 0 scans the 148 partials ----
    if (bid == 0) {
        int v = (tid < NBLK) ? g_part[tid] : 0;
        sci[tid] = v;
        __syncthreads();
        for (int off = 1; off < 256; off <<= 1) {
            int t_ = (tid >= off && tid < 256) ? sci[tid - off] : 0;
            __syncthreads();
            if (tid < 256) sci[tid] += t_;
            __syncthreads();
        }
        if (tid < NBLK) g_part[tid] = sci[tid] - v;
    }
    gsync(base + ++rnd);

    // ---- P4: globalize rowptr + init cursor ----
    {
        const int CH = (n + NBLK - 1) / NBLK;
        const int bbase = bid * CH;
        const int lim = (bbase + CH < n) ? bbase + CH : n;
        const int off = g_part[bid];
        int i0 = bbase + 2 * tid, i1 = i0 + 1;
        if (i0 < lim) { int v = g_rowptr[i0] + off; g_rowptr[i0] = v; g_cursor[i0] = v; }
        if (i1 < lim) { int v = g_rowptr[i1] + off; g_rowptr[i1] = v; g_cursor[i1] = v; }
        if (gt == 0) g_rowptr[n] = E;
    }
    gsync(base + ++rnd);

    // ---- P5: build CSR (packed edge meta) + edge-parallel agg of raw features ----
    for (int e = gt; e < E; e += GSTRIDE) {
        int s = src[e], d = dst[e];
        float nr = g_dinv[s] * g_dinv[d];
        int p = atomicAdd(&g_cursor[d], 1);
        g_edge[p] = make_int2(s, __float_as_int(nr));
        const float* xs = x + s * 9;
        float* ad = g_a9 + d * 9;
#pragma unroll
        for (int f = 0; f < 9; f++) atomicAdd(ad + f, xs[f] * nr);  // REDG, fire+forget
    }
    gsync(base + ++rnd);

    // ---- P6: 9->128 GEMM + self term + tanh -> bufA ----
    {
        float4* Ws4 = (float4*)smraw;                 // 9*32 float4
        const float4* W4 = (const float4*)W_in;
        for (int i = tid; i < 9 * 32; i += NTHR) Ws4[i] = W4[i];
        if (tid < 128) bs[tid] = b_in[tid];
        __syncthreads();
        for (int w = gw; w < n; w += NWARP) {
            float dv = g_dinv[w];
            float sn = dv * dv;
            float a[9];
#pragma unroll
            for (int f = 0; f < 9; f++) a[f] = g_a9[w * 9 + f] + x[w * 9 + f] * sn;
            float4 acc = ((const float4*)bs)[lane];
#pragma unroll
            for (int f = 0; f < 9; f++) {
                float4 wv = Ws4[f * 32 + lane];
                acc.x += a[f] * wv.x; acc.y += a[f] * wv.y;
                acc.z += a[f] * wv.z; acc.w += a[f] * wv.w;
            }
            acc.x = ftanh(acc.x); acc.y = ftanh(acc.y);
            acc.z = ftanh(acc.z); acc.w = ftanh(acc.w);
            ((float4*)g_bufA)[w * 32 + lane] = acc;
        }
    }
    gsync(base + ++rnd);

    // ---- P7..P11: two GCN layers + Wf1 ----
    agg128(g_bufA, g_bufB, n);
    gsync(base + ++rnd);
    gemm128_tanh(g_bufB, W1, b1, g_bufA, n, WpU, bs);
    gsync(base + ++rnd);
    agg128(g_bufA, g_bufB, n);
    gsync(base + ++rnd);
    gemm128_tanh(g_bufB, W2, b2, g_bufA, n, WpU, bs);
    gsync(base + ++rnd);
    gemm128_tanh(g_bufA, Wf1, bf1, g_bufB, n, WpU, bs);
    gsync(base + ++rnd);

    // ---- P12: fused head (Wf2 tanh, Wf3 dot) + pooled atomics ----
    {
        float* W2s = (float*)smraw;                  // 128*32 floats = 16 KB
        for (int i = tid; i < 128 * 32; i += NTHR) W2s[i] = Wf2[i];
        if (tid < 32) { bs[tid] = bf2[tid]; bs[32 + tid] = Wf3[tid]; }
        if (tid == 0) bs[64] = bf3[0];
        __syncthreads();
        for (int w = gw; w < n; w += NWARP) {
            const float4* hp = (const float4*)(g_bufB + w * 128);
            float acc = 0.0f;
#pragma unroll 8
            for (int f0 = 0; f0 < 128; f0 += 4) {
                float4 a = hp[f0 >> 2];
                acc += a.x * W2s[(f0 + 0) * 32 + lane];
                acc += a.y * W2s[(f0 + 1) * 32 + lane];
                acc += a.z * W2s[(f0 + 2) * 32 + lane];
                acc += a.w * W2s[(f0 + 3) * 32 + lane];
            }
            float t = ftanh(acc + bs[lane]);
            float v = t * bs[32 + lane];
#pragma unroll
            for (int off = 16; off > 0; off >>= 1)
                v += __shfl_xor_sync(0xffffffffu, v, off);
            if (lane == 0) {
                float s = v + bs[64];
                int g = batch[w];
                atomicAdd(&g_usum[g], s);
                atomicAdd(&g_ucnt[g], 1.0f);
            }
        }
    }
    gsync(base + ++rnd);

    // ---- P13: finalize util + pairwise sigmoid (merged) ----
    if (gt < G) {
        out[P + gt] = g_usum[gt] / fmaxf(g_ucnt[gt], 1.0f);
    }
    if (gt < P) {
        int ga = ia[gt], gb = ib[gt];
        float ua = g_usum[ga] / fmaxf(g_ucnt[ga], 1.0f);
        float ub = g_usum[gb] / fmaxf(g_ucnt[gb], 1.0f);
        float d = ub - ua;
        out[gt] = 1.0f / (1.0f + expf(-d));
    }
}

// ---------------- launch ----------------
extern "C" void kernel_launch(void* const* d_in, const int* in_sizes, int n_in,
                              void* d_out, int out_size) {
    const float* x     = (const float*)d_in[0];
    const int*   ei    = (const int*)d_in[1];
    const int*   batch = (const int*)d_in[2];
    const int*   ia    = (const int*)d_in[3];
    const int*   ib    = (const int*)d_in[4];
    const float* W_in  = (const float*)d_in[5];
    const float* b_in  = (const float*)d_in[6];
    const float* W1    = (const float*)d_in[7];
    const float* b1    = (const float*)d_in[8];
    const float* W2    = (const float*)d_in[9];
    const float* b2    = (const float*)d_in[10];
    const float* Wf1   = (const float*)d_in[11];
    const float* bf1   = (const float*)d_in[12];
    const float* Wf2   = (const float*)d_in[13];
    const float* bf2   = (const float*)d_in[14];
    const float* Wf3   = (const float*)d_in[15];
    const float* bf3   = (const float*)d_in[16];
    float* out = (float*)d_out;

    int n = in_sizes[0] / 9;
    int E = in_sizes[1] / 2;
    int P = in_sizes[3];
    int G = out_size - P;

    cudaFuncSetAttribute(mega, cudaFuncAttributeMaxDynamicSharedMemorySize, 67584);

    mega<<<NBLK, NTHR, 67584>>>(x, ei, batch, ia, ib, W_in, b_in, W1, b1, W2, b2,
                                Wf1, bf1, Wf2, bf2, Wf3, bf3, out, n, E, P, G);
}

// round 11
// speedup vs baseline: 1.0680x; 1.0680x over previous
#include <cuda_runtime.h>
#include <math.h>

#define NN 100000
#define EE 1600000
#define GG 2000
#define NBLK 148
#define NTHR 512
#define NWARP (NBLK * NTHR / 32)

// ---------------- scratch (device globals; allocation-free) ----------------
__device__ float g_bufA[NN * 128];
__device__ float g_bufB[NN * 128];
__device__ float g_dinv[NN];
__device__ int   g_deg[NN];
__device__ int   g_rowptr[NN + 1];
__device__ int   g_cursor[NN];
__device__ int2  g_edge[EE];            // {src, __float_as_int(norm)}
__device__ float g_usum[GG];
__device__ float g_ucnt[GG];
__device__ int   g_part[NBLK];
__device__ unsigned long long g_arrive;          // cumulative arrivals (persists across replays)
__device__ volatile unsigned  g_release;         // cumulative completed rounds

// ---------------- helpers ----------------
typedef unsigned long long ull;

__device__ __forceinline__ ull f2pack(float lo, float hi) {
    ull r;
    asm("mov.b64 %0, {%1, %2};" : "=l"(r) : "f"(lo), "f"(hi));
    return r;
}
__device__ __forceinline__ ull f2fma(ull a, ull b, ull c) {
    ull d;
    asm("fma.rn.f32x2 %0, %1, %2, %3;" : "=l"(d) : "l"(a), "l"(b), "l"(c));
    return d;
}
__device__ __forceinline__ void f2unpack(ull v, float& lo, float& hi) {
    asm("mov.b64 {%0, %1}, %2;" : "=f"(lo), "=f"(hi) : "l"(v));
}

// Fast tanh via MUFU.EX2 path; rel err ~1e-6. R7/R8 bit-identical rel_err proved
// this contributes ~1e-6 in quadrature (the 1.44e-3 was the GEMM column bug).
__device__ __forceinline__ float ftanh(float x) {
    float t = fminf(fmaxf(2.0f * x, -30.0f), 30.0f);
    float e = __expf(t);
    return 1.0f - __fdividef(2.0f, e + 1.0f);
}

// ---------------- grid barrier (cumulative, replay-safe) ----------------
__device__ __forceinline__ void gsync(unsigned target) {
    __threadfence();
    __syncthreads();
    if (threadIdx.x == 0) {
        ull a = atomicAdd(&g_arrive, 1ULL) + 1ULL;
        if ((a % (ull)NBLK) == 0ULL)
            g_release = (unsigned)(a / (ull)NBLK);
        while (g_release < target) __nanosleep(64);
        __threadfence();
    }
    __syncthreads();
}

// ---------------- GEMM: C = tanh(A[n x 128] @ W[128 x 128] + bias) ----------------
// Tile: 128 nodes x 128 cols per block iteration.
// Thread = 8 nodes (ty*8..+7) x 4 cols {tx, tx+32, tx+64, tx+96}. Full tile covered.
// W staged in smem f-pair-interleaved: Wp[fp*128+c] = (W[2fp][c], W[2fp+1][c]);
// LDS.64 lane-stride 8B (conflict-free). acc = (even-f sum, odd-f sum), lo+hi at epilogue.
__device__ __forceinline__ void gemm128_tanh(const float* __restrict__ A,
                                             const float* __restrict__ W,
                                             const float* __restrict__ bias,
                                             float* __restrict__ C, int n,
                                             ull* WpU, float* bs) {
    const int tid = threadIdx.x;
    {
        float2* Wp = (float2*)WpU;
        for (int i = tid; i < 64 * 128; i += NTHR) {
            int fp = i >> 7, c = i & 127;
            Wp[i] = make_float2(W[(2 * fp) * 128 + c], W[(2 * fp + 1) * 128 + c]);
        }
        if (tid < 128) bs[tid] = bias[tid];
    }
    __syncthreads();

    const int tx = tid & 31;      // cols tx, tx+32, tx+64, tx+96
    const int ty = tid >> 5;      // nodes ty*8 .. ty*8+7 within tile
    const int ntile = (n + 127) >> 7;
    const float4* A4 = (const float4*)A;

    for (int t = blockIdx.x; t < ntile; t += NBLK) {
        const int m0 = t * 128 + ty * 8;
        int mi[8];
#pragma unroll
        for (int j = 0; j < 8; j++) {
            int m = m0 + j;
            mi[j] = (m < n) ? m : (n - 1);
        }
        ull acc[8][4];
#pragma unroll
        for (int j = 0; j < 8; j++)
#pragma unroll
            for (int k = 0; k < 4; k++) acc[j][k] = 0ULL;

        for (int fg = 0; fg < 32; fg++) {
            ull WA[4], WB[4];
#pragma unroll
            for (int k = 0; k < 4; k++) {
                WA[k] = WpU[(2 * fg) * 128 + tx + 32 * k];       // f = 4fg, 4fg+1
                WB[k] = WpU[(2 * fg + 1) * 128 + tx + 32 * k];   // f = 4fg+2, 4fg+3
            }
#pragma unroll
            for (int j = 0; j < 8; j++) {
                float4 a = A4[mi[j] * 32 + fg];   // warp-uniform broadcast
                ull pa = f2pack(a.x, a.y);
                ull pb = f2pack(a.z, a.w);
#pragma unroll
                for (int k = 0; k < 4; k++) {
                    acc[j][k] = f2fma(pa, WA[k], acc[j][k]);
                    acc[j][k] = f2fma(pb, WB[k], acc[j][k]);
                }
            }
        }

#pragma unroll
        for (int j = 0; j < 8; j++) {
            int m = m0 + j;
            if (m < n) {
#pragma unroll
                for (int k = 0; k < 4; k++) {
                    float lo, hi;
                    f2unpack(acc[j][k], lo, hi);
                    int c = tx + 32 * k;
                    C[m * 128 + c] = ftanh(lo + hi + bs[c]);
                }
            }
        }
    }
    __syncthreads();
}

// warp-per-node 128-wide gather-aggregate
__device__ __forceinline__ void agg128(const float* __restrict__ h, float* __restrict__ out,
                                       int n) {
    int gw = (blockIdx.x * NTHR + threadIdx.x) >> 5;
    int lane = threadIdx.x & 31;
    const float4* h4 = (const float4*)h;
    for (int w = gw; w < n; w += NWARP) {
        float d = g_dinv[w];
        float sn = d * d;
        float4 v = h4[w * 32 + lane];
        float ax = v.x * sn, ay = v.y * sn, az = v.z * sn, aw = v.w * sn;
        int e = g_rowptr[w], end = g_rowptr[w + 1];
        for (; e + 4 <= end; e += 4) {
            int2 m0 = g_edge[e],     m1 = g_edge[e + 1];
            int2 m2 = g_edge[e + 2], m3 = g_edge[e + 3];
            float e0 = __int_as_float(m0.y), e1 = __int_as_float(m1.y);
            float e2 = __int_as_float(m2.y), e3 = __int_as_float(m3.y);
            float4 u0 = h4[m0.x * 32 + lane];
            float4 u1 = h4[m1.x * 32 + lane];
            float4 u2 = h4[m2.x * 32 + lane];
            float4 u3 = h4[m3.x * 32 + lane];
            ax += u0.x * e0; ay += u0.y * e0; az += u0.z * e0; aw += u0.w * e0;
            ax += u1.x * e1; ay += u1.y * e1; az += u1.z * e1; aw += u1.w * e1;
            ax += u2.x * e2; ay += u2.y * e2; az += u2.z * e2; aw += u2.w * e2;
            ax += u3.x * e3; ay += u3.y * e3; az += u3.z * e3; aw += u3.w * e3;
        }
        for (; e < end; e++) {
            int2 m = g_edge[e];
            float wt = __int_as_float(m.y);
            float4 u = h4[m.x * 32 + lane];
            ax += u.x * wt; ay += u.y * wt; az += u.z * wt; aw += u.w * wt;
        }
        float4 o; o.x = ax; o.y = ay; o.z = az; o.w = aw;
        ((float4*)out)[w * 32 + lane] = o;
    }
}

// ---------------- the mega kernel ----------------
__global__ void __launch_bounds__(NTHR, 1)
mega(const float* __restrict__ x, const int* __restrict__ ei, const int* __restrict__ batch,
     const int* __restrict__ ia, const int* __restrict__ ib,
     const float* __restrict__ W_in, const float* __restrict__ b_in,
     const float* __restrict__ W1, const float* __restrict__ b1,
     const float* __restrict__ W2, const float* __restrict__ b2,
     const float* __restrict__ Wf1, const float* __restrict__ bf1,
     const float* __restrict__ Wf2, const float* __restrict__ bf2,
     const float* __restrict__ Wf3, const float* __restrict__ bf3,
     float* __restrict__ out, int n, int E, int P, int G) {
    extern __shared__ unsigned char smraw[];
    ull*   WpU = (ull*)smraw;                      // 64 KB weight stage
    float* bs  = (float*)(smraw + 65536);          // 512 B bias / small params
    int*   sci = (int*)(smraw + 65536);            // 2 KB scan scratch (phase-disjoint)

    const int tid = threadIdx.x;
    const int bid = blockIdx.x;
    const int gt  = bid * NTHR + tid;
    const int GSTRIDE = NBLK * NTHR;
    const int lane = tid & 31;
    const int gw = gt >> 5;
    const int* src = ei;
    const int* dst = ei + E;

    __shared__ unsigned s_base;
    if (tid == 0) s_base = g_release;
    __syncthreads();
    const unsigned base = s_base;
    unsigned rnd = 0;

    // ---- P0: zero deg + pooled sums ----
    for (int i = gt; i < n; i += GSTRIDE) g_deg[i] = 0;
    if (gt < G) { g_usum[gt] = 0.0f; g_ucnt[gt] = 0.0f; }
    gsync(base + ++rnd);

    // ---- P1: in-degree count ----
    for (int e = gt; e < E; e += GSTRIDE) atomicAdd(&g_deg[dst[e]], 1);
    gsync(base + ++rnd);

    // ---- P2: block-local scan of deg -> rowptr (local excl), dinv, partials ----
    {
        const int CH = (n + NBLK - 1) / NBLK;
        const int bbase = bid * CH;
        const int lim = (bbase + CH < n) ? bbase + CH : n;
        int i0 = bbase + 2 * tid, i1 = i0 + 1;
        int v0 = (i0 < lim) ? g_deg[i0] : 0;
        int v1 = (i1 < lim) ? g_deg[i1] : 0;
        if (i0 < lim) g_dinv[i0] = rsqrtf((float)v0 + 1.0f);
        if (i1 < lim) g_dinv[i1] = rsqrtf((float)v1 + 1.0f);
        int s = v0 + v1;
        sci[tid] = s;
        __syncthreads();
        for (int off = 1; off < NTHR; off <<= 1) {
            int t_ = (tid >= off) ? sci[tid - off] : 0;
            __syncthreads();
            sci[tid] += t_;
            __syncthreads();
        }
        int exc = sci[tid] - s;
        if (i0 < lim) g_rowptr[i0] = exc;
        if (i1 < lim) g_rowptr[i1] = exc + v0;
        if (tid == NTHR - 1) g_part[bid] = sci[NTHR - 1];
    }
    gsync(base + ++rnd);

    // ---- P3: block 0 scans the 148 partials ----
    if (bid == 0) {
        int v = (tid < NBLK) ? g_part[tid] : 0;
        sci[tid] = v;
        __syncthreads();
        for (int off = 1; off < 256; off <<= 1) {
            int t_ = (tid >= off && tid < 256) ? sci[tid - off] : 0;
            __syncthreads();
            if (tid < 256) sci[tid] += t_;
            __syncthreads();
        }
        if (tid < NBLK) g_part[tid] = sci[tid] - v;
    }
    gsync(base + ++rnd);

    // ---- P4: globalize rowptr + init cursor ----
    {
        const int CH = (n + NBLK - 1) / NBLK;
        const int bbase = bid * CH;
        const int lim = (bbase + CH < n) ? bbase + CH : n;
        const int off = g_part[bid];
        int i0 = bbase + 2 * tid, i1 = i0 + 1;
        if (i0 < lim) { int v = g_rowptr[i0] + off; g_rowptr[i0] = v; g_cursor[i0] = v; }
        if (i1 < lim) { int v = g_rowptr[i1] + off; g_rowptr[i1] = v; g_cursor[i1] = v; }
        if (gt == 0) g_rowptr[n] = E;
    }
    gsync(base + ++rnd);

    // ---- P5: build CSR (packed edge meta only — NO scattered atomics) ----
    for (int e = gt; e < E; e += GSTRIDE) {
        int s = src[e], d = dst[e];
        float nr = g_dinv[s] * g_dinv[d];
        int p = atomicAdd(&g_cursor[d], 1);
        g_edge[p] = make_int2(s, __float_as_int(nr));
    }
    gsync(base + ++rnd);

    // ---- P6: fused agg9 + 9->128 GEMM + tanh -> bufA ----
    // Warp per node: lanes 0-8 aggregate the 9 raw features over CSR edges,
    // shfl-broadcast, then every lane computes 4 output columns.
    {
        float4* Ws4 = (float4*)smraw;                 // 9*32 float4
        const float4* W4 = (const float4*)W_in;
        for (int i = tid; i < 9 * 32; i += NTHR) Ws4[i] = W4[i];
        if (tid < 128) bs[tid] = b_in[tid];
        __syncthreads();
        for (int w = gw; w < n; w += NWARP) {
            float dv = g_dinv[w];
            float sn = dv * dv;
            float acc = 0.0f;
            if (lane < 9) {
                acc = x[w * 9 + lane] * sn;
                int e = g_rowptr[w], end = g_rowptr[w + 1];
                for (; e + 2 <= end; e += 2) {
                    int2 m0 = g_edge[e], m1 = g_edge[e + 1];
                    acc += x[m0.x * 9 + lane] * __int_as_float(m0.y);
                    acc += x[m1.x * 9 + lane] * __int_as_float(m1.y);
                }
                for (; e < end; e++) {
                    int2 m = g_edge[e];
                    acc += x[m.x * 9 + lane] * __int_as_float(m.y);
                }
            }
            float af[9];
#pragma unroll
            for (int f = 0; f < 9; f++) af[f] = __shfl_sync(0xffffffffu, acc, f);
            float4 o = ((const float4*)bs)[lane];
#pragma unroll
            for (int f = 0; f < 9; f++) {
                float4 wv = Ws4[f * 32 + lane];
                o.x += af[f] * wv.x; o.y += af[f] * wv.y;
                o.z += af[f] * wv.z; o.w += af[f] * wv.w;
            }
            o.x = ftanh(o.x); o.y = ftanh(o.y);
            o.z = ftanh(o.z); o.w = ftanh(o.w);
            ((float4*)g_bufA)[w * 32 + lane] = o;
        }
    }
    gsync(base + ++rnd);

    // ---- P7..P11: two GCN layers + Wf1 ----
    agg128(g_bufA, g_bufB, n);
    gsync(base + ++rnd);
    gemm128_tanh(g_bufB, W1, b1, g_bufA, n, WpU, bs);
    gsync(base + ++rnd);
    agg128(g_bufA, g_bufB, n);
    gsync(base + ++rnd);
    gemm128_tanh(g_bufB, W2, b2, g_bufA, n, WpU, bs);
    gsync(base + ++rnd);
    gemm128_tanh(g_bufA, Wf1, bf1, g_bufB, n, WpU, bs);
    gsync(base + ++rnd);

    // ---- P12: fused head (Wf2 tanh, Wf3 dot) + pooled atomics ----
    {
        float* W2s = (float*)smraw;                  // 128*32 floats = 16 KB
        for (int i = tid; i < 128 * 32; i += NTHR) W2s[i] = Wf2[i];
        if (tid < 32) { bs[tid] = bf2[tid]; bs[32 + tid] = Wf3[tid]; }
        if (tid == 0) bs[64] = bf3[0];
        __syncthreads();
        for (int w = gw; w < n; w += NWARP) {
            const float4* hp = (const float4*)(g_bufB + w * 128);
            float acc = 0.0f;
#pragma unroll 8
            for (int f0 = 0; f0 < 128; f0 += 4) {
                float4 a = hp[f0 >> 2];
                acc += a.x * W2s[(f0 + 0) * 32 + lane];
                acc += a.y * W2s[(f0 + 1) * 32 + lane];
                acc += a.z * W2s[(f0 + 2) * 32 + lane];
                acc += a.w * W2s[(f0 + 3) * 32 + lane];
            }
            float t = ftanh(acc + bs[lane]);
            float v = t * bs[32 + lane];
#pragma unroll
            for (int off = 16; off > 0; off >>= 1)
                v += __shfl_xor_sync(0xffffffffu, v, off);
            if (lane == 0) {
                float s = v + bs[64];
                int g = batch[w];
                atomicAdd(&g_usum[g], s);
                atomicAdd(&g_ucnt[g], 1.0f);
            }
        }
    }
    gsync(base + ++rnd);

    // ---- P13: finalize util + pairwise sigmoid (merged) ----
    if (gt < G) {
        out[P + gt] = g_usum[gt] / fmaxf(g_ucnt[gt], 1.0f);
    }
    if (gt < P) {
        int ga = ia[gt], gb = ib[gt];
        float ua = g_usum[ga] / fmaxf(g_ucnt[ga], 1.0f);
        float ub = g_usum[gb] / fmaxf(g_ucnt[gb], 1.0f);
        float d = ub - ua;
        out[gt] = 1.0f / (1.0f + expf(-d));
    }
}

// ---------------- launch ----------------
extern "C" void kernel_launch(void* const* d_in, const int* in_sizes, int n_in,
                              void* d_out, int out_size) {
    const float* x     = (const float*)d_in[0];
    const int*   ei    = (const int*)d_in[1];
    const int*   batch = (const int*)d_in[2];
    const int*   ia    = (const int*)d_in[3];
    const int*   ib    = (const int*)d_in[4];
    const float* W_in  = (const float*)d_in[5];
    const float* b_in  = (const float*)d_in[6];
    const float* W1    = (const float*)d_in[7];
    const float* b1    = (const float*)d_in[8];
    const float* W2    = (const float*)d_in[9];
    const float* b2    = (const float*)d_in[10];
    const float* Wf1   = (const float*)d_in[11];
    const float* bf1   = (const float*)d_in[12];
    const float* Wf2   = (const float*)d_in[13];
    const float* bf2   = (const float*)d_in[14];
    const float* Wf3   = (const float*)d_in[15];
    const float* bf3   = (const float*)d_in[16];
    float* out = (float*)d_out;

    int n = in_sizes[0] / 9;
    int E = in_sizes[1] / 2;
    int P = in_sizes[3];
    int G = out_size - P;

    cudaFuncSetAttribute(mega, cudaFuncAttributeMaxDynamicSharedMemorySize, 67584);

    mega<<<NBLK, NTHR, 67584>>>(x, ei, batch, ia, ib, W_in, b_in, W1, b1, W2, b2,
                                Wf1, bf1, Wf2, bf2, Wf3, bf3, out, n, E, P, G);
}

// round 12
// speedup vs baseline: 1.1979x; 1.1217x over previous
#include <cuda_runtime.h>
#include <math.h>

#define NN 100000
#define EE 1600000
#define GG 2000
#define NBLK 148
#define NTHR 768
#define NWARP (NBLK * NTHR / 32)

// ---------------- scratch (device globals; allocation-free) ----------------
__device__ float g_bufA[NN * 128];
__device__ float g_bufB[NN * 128];
__device__ float g_dinv[NN];
__device__ int   g_deg[NN];
__device__ int   g_rowptr[NN + 1];
__device__ int   g_cursor[NN];
__device__ int2  g_edge[EE];            // {src, __float_as_int(norm)}
__device__ float g_usum[GG];
__device__ float g_ucnt[GG];
__device__ int   g_part[NBLK];
__device__ unsigned long long g_arrive;          // cumulative arrivals (persists across replays)
__device__ volatile unsigned  g_release;         // cumulative completed rounds

// ---------------- helpers ----------------
typedef unsigned long long ull;

__device__ __forceinline__ ull f2pack(float lo, float hi) {
    ull r;
    asm("mov.b64 %0, {%1, %2};" : "=l"(r) : "f"(lo), "f"(hi));
    return r;
}
__device__ __forceinline__ ull f2fma(ull a, ull b, ull c) {
    ull d;
    asm("fma.rn.f32x2 %0, %1, %2, %3;" : "=l"(d) : "l"(a), "l"(b), "l"(c));
    return d;
}
__device__ __forceinline__ void f2unpack(ull v, float& lo, float& hi) {
    asm("mov.b64 {%0, %1}, %2;" : "=f"(lo), "=f"(hi) : "l"(v));
}

// Fast tanh via MUFU.EX2 path; rel err ~1e-6 (R7/R8 proved this is invisible
// next to the 1e-7 baseline error at the 1e-3 threshold).
__device__ __forceinline__ float ftanh(float x) {
    float t = fminf(fmaxf(2.0f * x, -30.0f), 30.0f);
    float e = __expf(t);
    return 1.0f - __fdividef(2.0f, e + 1.0f);
}

// ---------------- grid barrier (cumulative, replay-safe) ----------------
__device__ __forceinline__ void gsync(unsigned target) {
    __threadfence();
    __syncthreads();
    if (threadIdx.x == 0) {
        ull a = atomicAdd(&g_arrive, 1ULL) + 1ULL;
        if ((a % (ull)NBLK) == 0ULL)
            g_release = (unsigned)(a / (ull)NBLK);
        while (g_release < target) __nanosleep(64);
        __threadfence();
    }
    __syncthreads();
}

// ---------------- GEMM: C = tanh(A[n x 128] @ W[128 x 128] + bias) ----------------
// Tile: 96 nodes x 128 cols per block iteration (768 thr * 16 outputs = 12288 = 96*128).
// Thread = 4 nodes (ty*4..+3) x 4 cols {tx, tx+32, tx+64, tx+96}.
// W staged in smem f-pair-interleaved: Wp[fp*128+c] = (W[2fp][c], W[2fp+1][c]);
// LDS.64 lane-stride 8B (conflict-free). acc = (even-f sum, odd-f sum), lo+hi at epilogue.
__device__ __forceinline__ void gemm128_tanh(const float* __restrict__ A,
                                             const float* __restrict__ W,
                                             const float* __restrict__ bias,
                                             float* __restrict__ C, int n,
                                             ull* WpU, float* bs) {
    const int tid = threadIdx.x;
    {
        float2* Wp = (float2*)WpU;
        for (int i = tid; i < 64 * 128; i += NTHR) {
            int fp = i >> 7, c = i & 127;
            Wp[i] = make_float2(W[(2 * fp) * 128 + c], W[(2 * fp + 1) * 128 + c]);
        }
        if (tid < 128) bs[tid] = bias[tid];
    }
    __syncthreads();

    const int tx = tid & 31;      // cols tx, tx+32, tx+64, tx+96
    const int ty = tid >> 5;      // 0..23 -> nodes ty*4 .. ty*4+3 within tile
    const int ntile = (n + 95) / 96;
    const float4* A4 = (const float4*)A;

    for (int t = blockIdx.x; t < ntile; t += NBLK) {
        const int m0 = t * 96 + ty * 4;
        int mi[4];
#pragma unroll
        for (int j = 0; j < 4; j++) {
            int m = m0 + j;
            mi[j] = (m < n) ? m : (n - 1);
        }
        ull acc[4][4];
#pragma unroll
        for (int j = 0; j < 4; j++)
#pragma unroll
            for (int k = 0; k < 4; k++) acc[j][k] = 0ULL;

#pragma unroll 2
        for (int fg = 0; fg < 32; fg++) {
            ull WA[4], WB[4];
#pragma unroll
            for (int k = 0; k < 4; k++) {
                WA[k] = WpU[(2 * fg) * 128 + tx + 32 * k];       // f = 4fg, 4fg+1
                WB[k] = WpU[(2 * fg + 1) * 128 + tx + 32 * k];   // f = 4fg+2, 4fg+3
            }
#pragma unroll
            for (int j = 0; j < 4; j++) {
                float4 a = A4[mi[j] * 32 + fg];   // warp-uniform broadcast
                ull pa = f2pack(a.x, a.y);
                ull pb = f2pack(a.z, a.w);
#pragma unroll
                for (int k = 0; k < 4; k++) {
                    acc[j][k] = f2fma(pa, WA[k], acc[j][k]);
                    acc[j][k] = f2fma(pb, WB[k], acc[j][k]);
                }
            }
        }

#pragma unroll
        for (int j = 0; j < 4; j++) {
            int m = m0 + j;
            if (m < n) {
#pragma unroll
                for (int k = 0; k < 4; k++) {
                    float lo, hi;
                    f2unpack(acc[j][k], lo, hi);
                    int c = tx + 32 * k;
                    C[m * 128 + c] = ftanh(lo + hi + bs[c]);
                }
            }
        }
    }
    __syncthreads();
}

// warp-per-node 128-wide gather-aggregate
__device__ __forceinline__ void agg128(const float* __restrict__ h, float* __restrict__ out,
                                       int n) {
    int gw = (blockIdx.x * NTHR + threadIdx.x) >> 5;
    int lane = threadIdx.x & 31;
    const float4* h4 = (const float4*)h;
    for (int w = gw; w < n; w += NWARP) {
        float d = g_dinv[w];
        float sn = d * d;
        float4 v = h4[w * 32 + lane];
        float ax = v.x * sn, ay = v.y * sn, az = v.z * sn, aw = v.w * sn;
        int e = g_rowptr[w], end = g_rowptr[w + 1];
        for (; e + 4 <= end; e += 4) {
            int2 m0 = g_edge[e],     m1 = g_edge[e + 1];
            int2 m2 = g_edge[e + 2], m3 = g_edge[e + 3];
            float e0 = __int_as_float(m0.y), e1 = __int_as_float(m1.y);
            float e2 = __int_as_float(m2.y), e3 = __int_as_float(m3.y);
            float4 u0 = h4[m0.x * 32 + lane];
            float4 u1 = h4[m1.x * 32 + lane];
            float4 u2 = h4[m2.x * 32 + lane];
            float4 u3 = h4[m3.x * 32 + lane];
            ax += u0.x * e0; ay += u0.y * e0; az += u0.z * e0; aw += u0.w * e0;
            ax += u1.x * e1; ay += u1.y * e1; az += u1.z * e1; aw += u1.w * e1;
            ax += u2.x * e2; ay += u2.y * e2; az += u2.z * e2; aw += u2.w * e2;
            ax += u3.x * e3; ay += u3.y * e3; az += u3.z * e3; aw += u3.w * e3;
        }
        for (; e < end; e++) {
            int2 m = g_edge[e];
            float wt = __int_as_float(m.y);
            float4 u = h4[m.x * 32 + lane];
            ax += u.x * wt; ay += u.y * wt; az += u.z * wt; aw += u.w * wt;
        }
        float4 o; o.x = ax; o.y = ay; o.z = az; o.w = aw;
        ((float4*)out)[w * 32 + lane] = o;
    }
}

// ---------------- the mega kernel ----------------
__global__ void __launch_bounds__(NTHR, 1)
mega(const float* __restrict__ x, const int* __restrict__ ei, const int* __restrict__ batch,
     const int* __restrict__ ia, const int* __restrict__ ib,
     const float* __restrict__ W_in, const float* __restrict__ b_in,
     const float* __restrict__ W1, const float* __restrict__ b1,
     const float* __restrict__ W2, const float* __restrict__ b2,
     const float* __restrict__ Wf1, const float* __restrict__ bf1,
     const float* __restrict__ Wf2, const float* __restrict__ bf2,
     const float* __restrict__ Wf3, const float* __restrict__ bf3,
     float* __restrict__ out, int n, int E, int P, int G) {
    extern __shared__ unsigned char smraw[];
    ull*   WpU = (ull*)smraw;                      // 64 KB weight stage
    float* bs  = (float*)(smraw + 65536);          // bias / small params (4 KB region)
    int*   sci = (int*)(smraw + 65536);            // scan scratch (phase-disjoint)

    const int tid = threadIdx.x;
    const int bid = blockIdx.x;
    const int gt  = bid * NTHR + tid;
    const int GSTRIDE = NBLK * NTHR;
    const int lane = tid & 31;
    const int gw = gt >> 5;
    const int* src = ei;
    const int* dst = ei + E;

    __shared__ unsigned s_base;
    if (tid == 0) s_base = g_release;
    __syncthreads();
    const unsigned base = s_base;
    unsigned rnd = 0;

    // ---- P0: zero deg + pooled sums ----
    for (int i = gt; i < n; i += GSTRIDE) g_deg[i] = 0;
    if (gt < G) { g_usum[gt] = 0.0f; g_ucnt[gt] = 0.0f; }
    gsync(base + ++rnd);

    // ---- P1: in-degree count ----
    for (int e = gt; e < E; e += GSTRIDE) atomicAdd(&g_deg[dst[e]], 1);
    gsync(base + ++rnd);

    // ---- P2: block-local scan of deg -> rowptr (local excl), dinv, partials ----
    {
        const int CH = (n + NBLK - 1) / NBLK;           // 676 <= 2*NTHR
        const int bbase = bid * CH;
        const int lim = (bbase + CH < n) ? bbase + CH : n;
        int i0 = bbase + 2 * tid, i1 = i0 + 1;
        int v0 = (i0 < lim) ? g_deg[i0] : 0;
        int v1 = (i1 < lim) ? g_deg[i1] : 0;
        if (i0 < lim) g_dinv[i0] = rsqrtf((float)v0 + 1.0f);
        if (i1 < lim) g_dinv[i1] = rsqrtf((float)v1 + 1.0f);
        int s = v0 + v1;
        sci[tid] = s;
        __syncthreads();
        for (int off = 1; off < NTHR; off <<= 1) {
            int t_ = (tid >= off) ? sci[tid - off] : 0;
            __syncthreads();
            sci[tid] += t_;
            __syncthreads();
        }
        int exc = sci[tid] - s;
        if (i0 < lim) g_rowptr[i0] = exc;
        if (i1 < lim) g_rowptr[i1] = exc + v0;
        if (tid == NTHR - 1) g_part[bid] = sci[NTHR - 1];
    }
    gsync(base + ++rnd);

    // ---- P3: block 0 scans the 148 partials ----
    if (bid == 0) {
        int v = (tid < NBLK) ? g_part[tid] : 0;
        if (tid < 256) sci[tid] = v;
        __syncthreads();
        for (int off = 1; off < 256; off <<= 1) {
            int t_ = (tid >= off && tid < 256) ? sci[tid - off] : 0;
            __syncthreads();
            if (tid < 256) sci[tid] += t_;
            __syncthreads();
        }
        if (tid < NBLK) g_part[tid] = sci[tid] - v;
    }
    gsync(base + ++rnd);

    // ---- P4: globalize rowptr + init cursor ----
    {
        const int CH = (n + NBLK - 1) / NBLK;
        const int bbase = bid * CH;
        const int lim = (bbase + CH < n) ? bbase + CH : n;
        const int off = g_part[bid];
        int i0 = bbase + 2 * tid, i1 = i0 + 1;
        if (i0 < lim) { int v = g_rowptr[i0] + off; g_rowptr[i0] = v; g_cursor[i0] = v; }
        if (i1 < lim) { int v = g_rowptr[i1] + off; g_rowptr[i1] = v; g_cursor[i1] = v; }
        if (gt == 0) g_rowptr[n] = E;
    }
    gsync(base + ++rnd);

    // ---- P5: build CSR (packed edge meta only) ----
    for (int e = gt; e < E; e += GSTRIDE) {
        int s = src[e], d = dst[e];
        float nr = g_dinv[s] * g_dinv[d];
        int p = atomicAdd(&g_cursor[d], 1);
        g_edge[p] = make_int2(s, __float_as_int(nr));
    }
    gsync(base + ++rnd);

    // ---- P6: fused agg9 + 9->128 GEMM + tanh -> bufA ----
    {
        float4* Ws4 = (float4*)smraw;                 // 9*32 float4
        const float4* W4 = (const float4*)W_in;
        for (int i = tid; i < 9 * 32; i += NTHR) Ws4[i] = W4[i];
        if (tid < 128) bs[4096 / 4 + tid] = b_in[tid];   // keep clear of Ws4
        __syncthreads();
        const float* bsn = bs + 1024;
        for (int w = gw; w < n; w += NWARP) {
            float dv = g_dinv[w];
            float sn = dv * dv;
            float acc = 0.0f;
            if (lane < 9) {
                acc = x[w * 9 + lane] * sn;
                int e = g_rowptr[w], end = g_rowptr[w + 1];
                for (; e + 2 <= end; e += 2) {
                    int2 m0 = g_edge[e], m1 = g_edge[e + 1];
                    acc += x[m0.x * 9 + lane] * __int_as_float(m0.y);
                    acc += x[m1.x * 9 + lane] * __int_as_float(m1.y);
                }
                for (; e < end; e++) {
                    int2 m = g_edge[e];
                    acc += x[m.x * 9 + lane] * __int_as_float(m.y);
                }
            }
            float af[9];
#pragma unroll
            for (int f = 0; f < 9; f++) af[f] = __shfl_sync(0xffffffffu, acc, f);
            float4 o = ((const float4*)bsn)[lane];
#pragma unroll
            for (int f = 0; f < 9; f++) {
                float4 wv = Ws4[f * 32 + lane];
                o.x += af[f] * wv.x; o.y += af[f] * wv.y;
                o.z += af[f] * wv.z; o.w += af[f] * wv.w;
            }
            o.x = ftanh(o.x); o.y = ftanh(o.y);
            o.z = ftanh(o.z); o.w = ftanh(o.w);
            ((float4*)g_bufA)[w * 32 + lane] = o;
        }
    }
    gsync(base + ++rnd);

    // ---- P7..P11: two GCN layers + Wf1 ----
    agg128(g_bufA, g_bufB, n);
    gsync(base + ++rnd);
    gemm128_tanh(g_bufB, W1, b1, g_bufA, n, WpU, bs);
    gsync(base + ++rnd);
    agg128(g_bufA, g_bufB, n);
    gsync(base + ++rnd);
    gemm128_tanh(g_bufB, W2, b2, g_bufA, n, WpU, bs);
    gsync(base + ++rnd);
    gemm128_tanh(g_bufA, Wf1, bf1, g_bufB, n, WpU, bs);
    gsync(base + ++rnd);

    // ---- P12: fused head (Wf2 tanh, Wf3 dot) + pooled atomics ----
    {
        float* W2s = (float*)smraw;                  // 128*32 floats = 16 KB
        for (int i = tid; i < 128 * 32; i += NTHR) W2s[i] = Wf2[i];
        if (tid < 32) { bs[tid] = bf2[tid]; bs[32 + tid] = Wf3[tid]; }
        if (tid == 0) bs[64] = bf3[0];
        __syncthreads();
        for (int w = gw; w < n; w += NWARP) {
            const float4* hp = (const float4*)(g_bufB + w * 128);
            float acc = 0.0f;
#pragma unroll 8
            for (int f0 = 0; f0 < 128; f0 += 4) {
                float4 a = hp[f0 >> 2];
                acc += a.x * W2s[(f0 + 0) * 32 + lane];
                acc += a.y * W2s[(f0 + 1) * 32 + lane];
                acc += a.z * W2s[(f0 + 2) * 32 + lane];
                acc += a.w * W2s[(f0 + 3) * 32 + lane];
            }
            float t = ftanh(acc + bs[lane]);
            float v = t * bs[32 + lane];
#pragma unroll
            for (int off = 16; off > 0; off >>= 1)
                v += __shfl_xor_sync(0xffffffffu, v, off);
            if (lane == 0) {
                float s = v + bs[64];
                int g = batch[w];
                atomicAdd(&g_usum[g], s);
                atomicAdd(&g_ucnt[g], 1.0f);
            }
        }
    }
    gsync(base + ++rnd);

    // ---- P13: finalize util + pairwise sigmoid (merged) ----
    if (gt < G) {
        out[P + gt] = g_usum[gt] / fmaxf(g_ucnt[gt], 1.0f);
    }
    if (gt < P) {
        int ga = ia[gt], gb = ib[gt];
        float ua = g_usum[ga] / fmaxf(g_ucnt[ga], 1.0f);
        float ub = g_usum[gb] / fmaxf(g_ucnt[gb], 1.0f);
        float d = ub - ua;
        out[gt] = 1.0f / (1.0f + expf(-d));
    }
}

// ---------------- launch ----------------
extern "C" void kernel_launch(void* const* d_in, const int* in_sizes, int n_in,
                              void* d_out, int out_size) {
    const float* x     = (const float*)d_in[0];
    const int*   ei    = (const int*)d_in[1];
    const int*   batch = (const int*)d_in[2];
    const int*   ia    = (const int*)d_in[3];
    const int*   ib    = (const int*)d_in[4];
    const float* W_in  = (const float*)d_in[5];
    const float* b_in  = (const float*)d_in[6];
    const float* W1    = (const float*)d_in[7];
    const float* b1    = (const float*)d_in[8];
    const float* W2    = (const float*)d_in[9];
    const float* b2    = (const float*)d_in[10];
    const float* Wf1   = (const float*)d_in[11];
    const float* bf1   = (const float*)d_in[12];
    const float* Wf2   = (const float*)d_in[13];
    const float* bf2   = (const float*)d_in[14];
    const float* Wf3   = (const float*)d_in[15];
    const float* bf3   = (const float*)d_in[16];
    float* out = (float*)d_out;

    int n = in_sizes[0] / 9;
    int E = in_sizes[1] / 2;
    int P = in_sizes[3];
    int G = out_size - P;

    cudaFuncSetAttribute(mega, cudaFuncAttributeMaxDynamicSharedMemorySize, 73728);

    mega<<<NBLK, NTHR, 73728>>>(x, ei, batch, ia, ib, W_in, b_in, W1, b1, W2, b2,
                                Wf1, bf1, Wf2, bf2, Wf3, bf3, out, n, E, P, G);
}